// round 1
// baseline (speedup 1.0000x reference)
#include <cuda_runtime.h>
#include <math.h>

// Problem constants
#define SQ   2048   // sequence length
#define HID  768    // hidden
#define BB   2      // batch
#define NH   12     // heads
#define DH   64     // head dim
#define RR   5      // structural deps
#define BN   24     // BB*NH

// ---------------- device scratch (allocation-free) ----------------
// qext: slot 0 = q, slots 1..5 = q @ bili[r]   [slot][bn][s][d]
__device__ float g_qext[(size_t)6 * BN * SQ * DH];     //  75.5 MB
__device__ float g_k   [(size_t)BN * SQ * DH];         //  12.6 MB
__device__ float g_v   [(size_t)BN * SQ * DH];         //  12.6 MB
__device__ float g_scores[(size_t)BN * SQ * SQ];       // 402.7 MB

// =================================================================
// Kernel 1: QKV projection.  out = X @ W^T + b, written in head layout.
// grid (12 otiles, 64 mtiles, 3 {q,k,v}), block 256, 4x4 microtile.
// =================================================================
__global__ __launch_bounds__(256) void proj_kernel(
    const float* __restrict__ X,
    const float* __restrict__ Wq, const float* __restrict__ Wk,
    const float* __restrict__ Wv,
    const float* __restrict__ bq, const float* __restrict__ bk,
    const float* __restrict__ bv)
{
    const int otile = blockIdx.x, mtile = blockIdx.y, z = blockIdx.z;
    const float* W    = (z == 0) ? Wq : (z == 1) ? Wk : Wv;
    const float* bias = (z == 0) ? bq : (z == 1) ? bk : bv;
    float* outp       = (z == 0) ? g_qext : (z == 1) ? g_k : g_v;

    __shared__ float Xs[16][68];   // [k][m]
    __shared__ float Ws[16][68];   // [k][o]

    const int t  = threadIdx.x;
    const int tx = t & 15, ty = t >> 4;
    const int lrow = t >> 2;          // 0..63
    const int lk4  = (t & 3) << 2;    // 0,4,8,12

    const float* Xbase = X + (size_t)(mtile * 64 + lrow) * HID;
    const float* Wbase = W + (size_t)(otile * 64 + lrow) * HID;

    float acc[4][4] = {};

    for (int k0 = 0; k0 < HID; k0 += 16) {
        float4 xv = *(const float4*)(Xbase + k0 + lk4);
        float4 wv = *(const float4*)(Wbase + k0 + lk4);
        __syncthreads();
        Xs[lk4 + 0][lrow] = xv.x; Xs[lk4 + 1][lrow] = xv.y;
        Xs[lk4 + 2][lrow] = xv.z; Xs[lk4 + 3][lrow] = xv.w;
        Ws[lk4 + 0][lrow] = wv.x; Ws[lk4 + 1][lrow] = wv.y;
        Ws[lk4 + 2][lrow] = wv.z; Ws[lk4 + 3][lrow] = wv.w;
        __syncthreads();
#pragma unroll
        for (int kk = 0; kk < 16; kk++) {
            float4 a = *(const float4*)&Xs[kk][ty << 2];
            float4 b = *(const float4*)&Ws[kk][tx << 2];
            acc[0][0] += a.x * b.x; acc[0][1] += a.x * b.y;
            acc[0][2] += a.x * b.z; acc[0][3] += a.x * b.w;
            acc[1][0] += a.y * b.x; acc[1][1] += a.y * b.y;
            acc[1][2] += a.y * b.z; acc[1][3] += a.y * b.w;
            acc[2][0] += a.z * b.x; acc[2][1] += a.z * b.y;
            acc[2][2] += a.z * b.z; acc[2][3] += a.z * b.w;
            acc[3][0] += a.w * b.x; acc[3][1] += a.w * b.y;
            acc[3][2] += a.w * b.z; acc[3][3] += a.w * b.w;
        }
    }

    // epilogue: n == otile (64-aligned tiles), d = tx*4+jj
    const int n = otile;
#pragma unroll
    for (int ii = 0; ii < 4; ii++) {
        int m = mtile * 64 + (ty << 2) + ii;
        int b = m / SQ, s = m % SQ;
        float* dst = outp + ((size_t)(b * NH + n) * SQ + s) * DH + (tx << 2);
        float4 o;
        o.x = acc[ii][0] + bias[otile * 64 + (tx << 2) + 0];
        o.y = acc[ii][1] + bias[otile * 64 + (tx << 2) + 1];
        o.z = acc[ii][2] + bias[otile * 64 + (tx << 2) + 2];
        o.w = acc[ii][3] + bias[otile * 64 + (tx << 2) + 3];
        *(float4*)dst = o;
    }
}

// =================================================================
// Kernel 2: q'_r = q @ bili[r,n].  grid (32 itiles, 24 bn, 5 r).
// =================================================================
__global__ __launch_bounds__(256) void qb_kernel(const float* __restrict__ bili)
{
    const int itile = blockIdx.x, bn = blockIdx.y, r = blockIdx.z;
    const int n = bn % NH;

    __shared__ float qs[64][68];    // [p][i]
    __shared__ float bs[64 * 64];   // [p][q] direct

    const int t  = threadIdx.x;
    const int tx = t & 15, ty = t >> 4;

    // load q tile transposed (64x64, 4 float4 per thread)
#pragma unroll
    for (int c = 0; c < 4; c++) {
        int id  = t + 256 * c;
        int row = id >> 4;
        int p4  = (id & 15) << 2;
        float4 v = *(const float4*)&g_qext[((size_t)bn * SQ + itile * 64 + row) * DH + p4];
        qs[p4 + 0][row] = v.x; qs[p4 + 1][row] = v.y;
        qs[p4 + 2][row] = v.z; qs[p4 + 3][row] = v.w;
    }
    // load bili[r][n] direct
    const float* bb = bili + ((size_t)r * NH + n) * DH * DH;
#pragma unroll
    for (int c = 0; c < 4; c++) {
        int id = t + 256 * c;
        *(float4*)&bs[id << 2] = *(const float4*)(bb + (id << 2));
    }
    __syncthreads();

    float acc[4][4] = {};
#pragma unroll 16
    for (int p = 0; p < 64; p++) {
        float4 a = *(const float4*)&qs[p][ty << 2];
        float4 b = *(const float4*)&bs[p * 64 + (tx << 2)];
        acc[0][0] += a.x * b.x; acc[0][1] += a.x * b.y;
        acc[0][2] += a.x * b.z; acc[0][3] += a.x * b.w;
        acc[1][0] += a.y * b.x; acc[1][1] += a.y * b.y;
        acc[1][2] += a.y * b.z; acc[1][3] += a.y * b.w;
        acc[2][0] += a.z * b.x; acc[2][1] += a.z * b.y;
        acc[2][2] += a.z * b.z; acc[2][3] += a.z * b.w;
        acc[3][0] += a.w * b.x; acc[3][1] += a.w * b.y;
        acc[3][2] += a.w * b.z; acc[3][3] += a.w * b.w;
    }

#pragma unroll
    for (int ii = 0; ii < 4; ii++) {
        int i = itile * 64 + (ty << 2) + ii;
        float4 o = make_float4(acc[ii][0], acc[ii][1], acc[ii][2], acc[ii][3]);
        *(float4*)&g_qext[(((size_t)(1 + r) * BN + bn) * SQ + i) * DH + (tx << 2)] = o;
    }
}

// =================================================================
// Kernel 3: fused score = q.k + sum_r adj_r*(q'_r.k + ab_r), scaled + mask.
// grid (32 jtiles, 32 itiles, 24 bn), block 256, 4x4 microtile.
// =================================================================
__global__ __launch_bounds__(256) void score_kernel(
    const float* __restrict__ adj,   // [R][B][1][S][S]
    const float* __restrict__ absb,  // [R][N]
    const float* __restrict__ mask)  // [B][1][1][S]
{
    const int jt = blockIdx.x, it = blockIdx.y, bn = blockIdx.z;
    const int b = bn / NH, n = bn % NH;

    __shared__ float ks[64][68];   // [d][j]
    __shared__ float qs[64][68];   // [d][i]

    const int t  = threadIdx.x;
    const int tx = t & 15, ty = t >> 4;

    // load k tile transposed (once)
#pragma unroll
    for (int c = 0; c < 4; c++) {
        int id  = t + 256 * c;
        int row = id >> 4;
        int p4  = (id & 15) << 2;
        float4 v = *(const float4*)&g_k[((size_t)bn * SQ + jt * 64 + row) * DH + p4];
        ks[p4 + 0][row] = v.x; ks[p4 + 1][row] = v.y;
        ks[p4 + 2][row] = v.z; ks[p4 + 3][row] = v.w;
    }

    float acc[4][4];

    for (int slot = 0; slot < 6; slot++) {
        __syncthreads();   // previous pass done before overwriting qs (also orders ks on slot 0)
#pragma unroll
        for (int c = 0; c < 4; c++) {
            int id  = t + 256 * c;
            int row = id >> 4;
            int p4  = (id & 15) << 2;
            float4 v = *(const float4*)&g_qext[(((size_t)slot * BN + bn) * SQ + it * 64 + row) * DH + p4];
            qs[p4 + 0][row] = v.x; qs[p4 + 1][row] = v.y;
            qs[p4 + 2][row] = v.z; qs[p4 + 3][row] = v.w;
        }
        __syncthreads();

        float tmp[4][4] = {};
#pragma unroll 16
        for (int p = 0; p < 64; p++) {
            float4 a = *(const float4*)&qs[p][ty << 2];
            float4 kb = *(const float4*)&ks[p][tx << 2];
            tmp[0][0] += a.x * kb.x; tmp[0][1] += a.x * kb.y;
            tmp[0][2] += a.x * kb.z; tmp[0][3] += a.x * kb.w;
            tmp[1][0] += a.y * kb.x; tmp[1][1] += a.y * kb.y;
            tmp[1][2] += a.y * kb.z; tmp[1][3] += a.y * kb.w;
            tmp[2][0] += a.z * kb.x; tmp[2][1] += a.z * kb.y;
            tmp[2][2] += a.z * kb.z; tmp[2][3] += a.z * kb.w;
            tmp[3][0] += a.w * kb.x; tmp[3][1] += a.w * kb.y;
            tmp[3][2] += a.w * kb.z; tmp[3][3] += a.w * kb.w;
        }

        if (slot == 0) {
#pragma unroll
            for (int ii = 0; ii < 4; ii++)
#pragma unroll
                for (int jj = 0; jj < 4; jj++) acc[ii][jj] = tmp[ii][jj];
        } else {
            const int r = slot - 1;
            const float ab = absb[r * NH + n];
#pragma unroll
            for (int ii = 0; ii < 4; ii++) {
                int ig = it * 64 + (ty << 2) + ii;
                float4 av = *(const float4*)&adj[(((size_t)r * BB + b) * SQ + ig) * SQ + jt * 64 + (tx << 2)];
                acc[ii][0] += av.x * (tmp[ii][0] + ab);
                acc[ii][1] += av.y * (tmp[ii][1] + ab);
                acc[ii][2] += av.z * (tmp[ii][2] + ab);
                acc[ii][3] += av.w * (tmp[ii][3] + ab);
            }
        }
    }

    // scale (1/sqrt(64)) + additive mask, write scores
    const float scale = 0.125f;
    float4 mk = *(const float4*)&mask[b * SQ + jt * 64 + (tx << 2)];
#pragma unroll
    for (int ii = 0; ii < 4; ii++) {
        int ig = it * 64 + (ty << 2) + ii;
        float4 o;
        o.x = acc[ii][0] * scale + mk.x;
        o.y = acc[ii][1] * scale + mk.y;
        o.z = acc[ii][2] * scale + mk.z;
        o.w = acc[ii][3] * scale + mk.w;
        *(float4*)&g_scores[((size_t)bn * SQ + ig) * SQ + jt * 64 + (tx << 2)] = o;
    }
}

// =================================================================
// Kernel 4: row softmax in place.  grid = BN*S blocks, 256 threads.
// =================================================================
__global__ __launch_bounds__(256) void softmax_kernel()
{
    const size_t row = blockIdx.x;
    float* p = g_scores + row * (size_t)SQ;
    const int t = threadIdx.x;

    float v[8];
    float m = -1e30f;
#pragma unroll
    for (int c = 0; c < 8; c++) {
        v[c] = p[t + 256 * c];
        m = fmaxf(m, v[c]);
    }
#pragma unroll
    for (int off = 16; off > 0; off >>= 1)
        m = fmaxf(m, __shfl_xor_sync(0xffffffffu, m, off));

    __shared__ float redm[8];
    __shared__ float reds[8];
    __shared__ float bcast[2];
    const int warp = t >> 5, lane = t & 31;
    if (lane == 0) redm[warp] = m;
    __syncthreads();
    if (t == 0) {
        float mm = redm[0];
#pragma unroll
        for (int w = 1; w < 8; w++) mm = fmaxf(mm, redm[w]);
        bcast[0] = mm;
    }
    __syncthreads();
    m = bcast[0];

    float s = 0.f;
#pragma unroll
    for (int c = 0; c < 8; c++) {
        v[c] = __expf(v[c] - m);
        s += v[c];
    }
#pragma unroll
    for (int off = 16; off > 0; off >>= 1)
        s += __shfl_xor_sync(0xffffffffu, s, off);
    if (lane == 0) reds[warp] = s;
    __syncthreads();
    if (t == 0) {
        float ss = 0.f;
#pragma unroll
        for (int w = 0; w < 8; w++) ss += reds[w];
        bcast[1] = 1.0f / ss;
    }
    __syncthreads();
    const float inv = bcast[1];
#pragma unroll
    for (int c = 0; c < 8; c++) p[t + 256 * c] = v[c] * inv;
}

// =================================================================
// Kernel 5: ctx = P @ V, write output in [b, s, n*64+d] layout.
// grid (32 itiles, 24 bn), block 256.
// =================================================================
__global__ __launch_bounds__(256) void ctx_kernel(float* __restrict__ out)
{
    const int it = blockIdx.x, bn = blockIdx.y;
    const int b = bn / NH, n = bn % NH;

    __shared__ float ps[64][68];   // [j][i]
    __shared__ float vs[64 * 64];  // [j][d]

    const int t  = threadIdx.x;
    const int tx = t & 15, ty = t >> 4;

    float acc[4][4] = {};

    for (int jt = 0; jt < 32; jt++) {
        __syncthreads();
#pragma unroll
        for (int c = 0; c < 4; c++) {
            int id  = t + 256 * c;
            int row = id >> 4;
            int q4  = (id & 15) << 2;
            float4 pv = *(const float4*)&g_scores[((size_t)bn * SQ + it * 64 + row) * SQ + jt * 64 + q4];
            ps[q4 + 0][row] = pv.x; ps[q4 + 1][row] = pv.y;
            ps[q4 + 2][row] = pv.z; ps[q4 + 3][row] = pv.w;
            float4 vv = *(const float4*)&g_v[((size_t)bn * SQ + jt * 64 + row) * DH + q4];
            *(float4*)&vs[row * 64 + q4] = vv;
        }
        __syncthreads();

#pragma unroll 16
        for (int j = 0; j < 64; j++) {
            float4 a  = *(const float4*)&ps[j][ty << 2];
            float4 bv = *(const float4*)&vs[j * 64 + (tx << 2)];
            acc[0][0] += a.x * bv.x; acc[0][1] += a.x * bv.y;
            acc[0][2] += a.x * bv.z; acc[0][3] += a.x * bv.w;
            acc[1][0] += a.y * bv.x; acc[1][1] += a.y * bv.y;
            acc[1][2] += a.y * bv.z; acc[1][3] += a.y * bv.w;
            acc[2][0] += a.z * bv.x; acc[2][1] += a.z * bv.y;
            acc[2][2] += a.z * bv.z; acc[2][3] += a.z * bv.w;
            acc[3][0] += a.w * bv.x; acc[3][1] += a.w * bv.y;
            acc[3][2] += a.w * bv.z; acc[3][3] += a.w * bv.w;
        }
    }

#pragma unroll
    for (int ii = 0; ii < 4; ii++) {
        int i = it * 64 + (ty << 2) + ii;
        float4 o = make_float4(acc[ii][0], acc[ii][1], acc[ii][2], acc[ii][3]);
        *(float4*)&out[((size_t)b * SQ + i) * HID + n * 64 + (tx << 2)] = o;
    }
}

// =================================================================
extern "C" void kernel_launch(void* const* d_in, const int* in_sizes, int n_in,
                              void* d_out, int out_size)
{
    const float* hidden = (const float*)d_in[0];
    const float* mask   = (const float*)d_in[1];
    const float* adj    = (const float*)d_in[2];
    const float* Wq     = (const float*)d_in[3];
    const float* bq     = (const float*)d_in[4];
    const float* Wk     = (const float*)d_in[5];
    const float* bk     = (const float*)d_in[6];
    const float* Wv     = (const float*)d_in[7];
    const float* bv     = (const float*)d_in[8];
    const float* bili   = (const float*)d_in[9];
    const float* absb   = (const float*)d_in[10];
    float* out = (float*)d_out;
    (void)in_sizes; (void)n_in; (void)out_size;

    proj_kernel<<<dim3(HID / 64, (BB * SQ) / 64, 3), 256>>>(hidden, Wq, Wk, Wv, bq, bk, bv);
    qb_kernel<<<dim3(SQ / 64, BN, RR), 256>>>(bili);
    score_kernel<<<dim3(SQ / 64, SQ / 64, BN), 256>>>(adj, absb, mask);
    softmax_kernel<<<BN * SQ, 256>>>();
    ctx_kernel<<<dim3(SQ / 64, BN), 256>>>(out);
}